// round 16
// baseline (speedup 1.0000x reference)
#include <cuda_runtime.h>
#include <math.h>

#define NPIX 2097152
#define NKEY 4913
#define NBLK 296
#define NTHR 256
#define TOTTHR (NBLK*NTHR)

// double accumulator offsets
#define OF_XMOM 0
#define OF_M0P  16
#define OF_M0PP 32
#define OF_MOM2 48
#define OF_ZM   200
#define OF_ZM2  296
#define OF_PZ   392
#define ACCN    512

__device__ unsigned char  g_qidx[8*3*512*512];
__device__ unsigned short g_key [NPIX];
__device__ unsigned int   g_hist[NKEY];
__device__ double g_acc[ACCN];
__device__ float  g_prepLUT[NKEY*16];
__device__ float  g_S[192], g_T[192];
// pyramid levels, CHANNEL-LAST: d[((b*n+y)*n+x)*16 + g]
__device__ float  g_d1[8*171*171*16];
__device__ float  g_d2[8*57*57*16];
__device__ float  g_d3[8*19*19*16];
__device__ float  g_d4[8*7*7*16];
__device__ float  g_d5[8*3*3*16];
__device__ float  g_d6[8*16];

// software grid barrier state (monotonic generation -> replay-safe)
__device__ unsigned int g_barcnt = 0;
__device__ unsigned int g_bargen = 0;

__constant__ int c_n[7] = {512,171,57,19,7,3,1};
// stats task layout: bx<256 -> cross0; then zstats lvl1..6, crossN it1..5
__constant__ int c_tstart[12] = {256,371,384,386,387,388,389,504,517,519,520,521};

__device__ __forceinline__ const float* dlevel(int l){
    switch(l){ case 1: return g_d1; case 2: return g_d2; case 3: return g_d3;
               case 4: return g_d4; case 5: return g_d5; default: return g_d6; }
}
__device__ __forceinline__ int qbin(float v){
    return (int)rintf(__fmul_rn(__fmul_rn(v, 255.0f), 0.0625f));
}
__device__ __forceinline__ unsigned char amax17(const unsigned int s[5]){
    int best = 0; unsigned int bc = s[0] & 255u;
    #pragma unroll
    for (int b = 1; b < 17; b++){
        unsigned int c = (s[b>>2] >> ((b&3)*8)) & 255u;
        if (c > bc){ bc = c; best = b; }
    }
    return (unsigned char)best;
}
__device__ __forceinline__ void ld16(const float* p, float* v){
    const float4* q = (const float4*)p;
    float4 a=q[0], b=q[1], c=q[2], d=q[3];
    v[0]=a.x; v[1]=a.y; v[2]=a.z; v[3]=a.w; v[4]=b.x; v[5]=b.y; v[6]=b.z; v[7]=b.w;
    v[8]=c.x; v[9]=c.y; v[10]=c.z; v[11]=c.w; v[12]=d.x; v[13]=d.y; v[14]=d.z; v[15]=d.w;
}
__device__ __forceinline__ void st16(float* p, const float* v){
    float4* q = (float4*)p;
    q[0]=make_float4(v[0],v[1],v[2],v[3]);   q[1]=make_float4(v[4],v[5],v[6],v[7]);
    q[2]=make_float4(v[8],v[9],v[10],v[11]); q[3]=make_float4(v[12],v[13],v[14],v[15]);
}
__device__ __forceinline__ void red16(const float* a, double* sm){
    #pragma unroll
    for (int j = 0; j < 16; j++){
        float v = a[j];
        #pragma unroll
        for (int off = 16; off; off >>= 1) v += __shfl_down_sync(0xffffffffu, v, off);
        if ((threadIdx.x & 31) == 0 && v != 0.f) atomicAdd(&sm[j], (double)v);
    }
}
__device__ __forceinline__ int wlo(int n, int r){ return (r*512 + n - 1)/n; }

__device__ __forceinline__ void gridbar(){
    __syncthreads();
    if (threadIdx.x == 0){
        __threadfence();
        unsigned int gen = *(volatile unsigned int*)&g_bargen;
        if (atomicAdd(&g_barcnt, 1u) == NBLK - 1u){
            g_barcnt = 0u;
            __threadfence();
            *(volatile unsigned int*)&g_bargen = gen + 1u;
        } else {
            while (*(volatile unsigned int*)&g_bargen == gen) __nanosleep(32);
        }
    }
    __syncthreads();
}

// BN1 affine from accumulated x-moments; threads 0..15 fill sA1[48], sB1[16]
__device__ __forceinline__ void bn1_affine_block(
    const float* __restrict__ pw1, const float* __restrict__ pb1,
    const float* __restrict__ g1,  const float* __restrict__ be1,
    float* sA1, float* sB1){
    int o = threadIdx.x;
    if (o < 16){
        double mom[9];
        #pragma unroll
        for (int i = 0; i < 9; i++) mom[i] = g_acc[OF_XMOM + i];
        const double N = (double)NPIX;
        double mu[3] = {mom[0]/N, mom[1]/N, mom[2]/N};
        double cov[3][3];
        cov[0][0]=mom[3]/N-mu[0]*mu[0]; cov[0][1]=mom[4]/N-mu[0]*mu[1]; cov[0][2]=mom[5]/N-mu[0]*mu[2];
        cov[1][1]=mom[6]/N-mu[1]*mu[1]; cov[1][2]=mom[7]/N-mu[1]*mu[2]; cov[2][2]=mom[8]/N-mu[2]*mu[2];
        cov[1][0]=cov[0][1]; cov[2][0]=cov[0][2]; cov[2][1]=cov[1][2];
        double wv[3] = {pw1[o*3], pw1[o*3+1], pw1[o*3+2]};
        double m = (double)pb1[o] + wv[0]*mu[0] + wv[1]*mu[1] + wv[2]*mu[2];
        double v = 0.0;
        for (int i = 0; i < 3; i++) for (int j = 0; j < 3; j++) v += wv[i]*wv[j]*cov[i][j];
        double s = (1.0 / sqrt(v + 1e-5)) * (double)g1[o];
        sA1[o*3+0]=(float)(wv[0]*s); sA1[o*3+1]=(float)(wv[1]*s); sA1[o*3+2]=(float)(wv[2]*s);
        sB1[o]=(float)(((double)pb1[o]-m)*s + (double)be1[o]);
    }
}

#define SWZ(c) ((c) + ((c)>>5))
#define SROW 528

// conv cell helper (channel-last)
__device__ __forceinline__ void conv_cell(const float* __restrict__ in, float* __restrict__ out,
                                          const float* __restrict__ sdw, int b, int n, int m,
                                          int u, int v){
    float acc[16];
    #pragma unroll
    for (int o = 0; o < 16; o++) acc[o] = 0.f;
    for (int ky = 0; ky < 3; ky++){
        int iy = 3*u - 1 + ky; if (iy < 0 || iy >= n) continue;
        for (int kx = 0; kx < 3; kx++){
            int ix = 3*v - 1 + kx; if (ix < 0 || ix >= n) continue;
            float pv[16];
            ld16(in + ((size_t)(b*n+iy)*n + ix)*16, pv);
            #pragma unroll
            for (int c = 0; c < 16; c++){
                #pragma unroll
                for (int o = 0; o < 16; o++)
                    acc[o] += sdw[(o*16+c)*9 + ky*3 + kx] * pv[c];
            }
        }
    }
    st16(out + ((size_t)(b*m+u)*m + v)*16, acc);
}

// =================== THE single persistent kernel ===================
__global__ void __launch_bounds__(NTHR, 2) k_all(
    const float* __restrict__ x,
    const float* __restrict__ pw1, const float* __restrict__ pb1,
    const float* __restrict__ g1,  const float* __restrict__ be1,
    const float* __restrict__ pw2, const float* __restrict__ pb2,
    const float* __restrict__ g2,  const float* __restrict__ be2,
    const float* __restrict__ dw,  const float* __restrict__ sw,
    const float* __restrict__ gs,  const float* __restrict__ bs,
    float* __restrict__ out)
{
    __shared__ __align__(16) unsigned char SM[21248];
    const int tid = threadIdx.x;
    const int bid = blockIdx.x;

    // ---------- Phase A: zero accumulators + 11x11 mode pool ----------
    if (bid == 0){
        for (int i = tid; i < NKEY; i += NTHR) g_hist[i] = 0u;
        for (int i = tid; i < ACCN; i += NTHR) g_acc[i] = 0.0;
    }
    {
        unsigned int* sh = (unsigned int*)SM;
        for (int tile = bid; tile < 384; tile += NBLK){
            int plane = tile / 16;
            int y0    = (tile % 16) * 32;
            const float* xp = x + (size_t)plane * 262144;
            unsigned char* qp = g_qidx + (size_t)plane * 262144;
            __syncthreads();
            for (int i = tid; i < 5*SROW; i += NTHR) sh[i] = 0u;
            __syncthreads();
            const int c0 = tid * 2;
            const int sc0 = SWZ(c0);           // c0 even -> SWZ(c0+1)=sc0+1
            for (int dy = -5; dy <= 5; dy++){
                int ry = y0 + dy; ry = ry < 0 ? -ry : (ry > 511 ? 1022 - ry : ry);
                float2 f = *(const float2*)(xp + ry*512 + c0);
                int b0 = qbin(f.x), b1 = qbin(f.y);
                sh[(b0>>2)*SROW + sc0]     += 1u << ((b0&3)*8);
                sh[(b1>>2)*SROW + sc0 + 1] += 1u << ((b1&3)*8);
            }
            __syncthreads();
            for (int r = 0; r < 32; r++){
                int y = y0 + r;
                if (r > 0){
                    int yr = y - 6; yr = yr < 0 ? -yr : yr;
                    int ya = y + 5; ya = ya > 511 ? 1022 - ya : ya;
                    float2 fr = *(const float2*)(xp + yr*512 + c0);
                    float2 fa = *(const float2*)(xp + ya*512 + c0);
                    int b0 = qbin(fr.x), b1 = qbin(fr.y);
                    sh[(b0>>2)*SROW + sc0]     -= 1u << ((b0&3)*8);
                    sh[(b1>>2)*SROW + sc0 + 1] -= 1u << ((b1&3)*8);
                    b0 = qbin(fa.x); b1 = qbin(fa.y);
                    sh[(b0>>2)*SROW + sc0]     += 1u << ((b0&3)*8);
                    sh[(b1>>2)*SROW + sc0 + 1] += 1u << ((b1&3)*8);
                    __syncthreads();
                }
                unsigned int s[5];
                #pragma unroll
                for (int w = 0; w < 5; w++){
                    unsigned int a = 0;
                    #pragma unroll
                    for (int j = -5; j <= 5; j++){
                        int cj = c0 + j; cj = cj < 0 ? -cj : (cj > 511 ? 1022 - cj : cj);
                        a += sh[w*SROW + SWZ(cj)];
                    }
                    s[w] = a;
                }
                unsigned char m0 = amax17(s);
                {
                    int c = c0 + 1;
                    int cr = c - 6; cr = cr < 0 ? -cr : cr;
                    int ca = c + 5; ca = ca > 511 ? 1022 - ca : ca;
                    #pragma unroll
                    for (int w = 0; w < 5; w++)
                        s[w] += sh[w*SROW + SWZ(ca)] - sh[w*SROW + SWZ(cr)];
                }
                unsigned char m1 = amax17(s);
                *(uchar2*)(qp + y*512 + c0) = make_uchar2(m0, m1);
                __syncthreads();
            }
        }
    }
    gridbar();

    // ---------- Phase B: keys + histogram + x-moments ----------
    {
        unsigned int* h = (unsigned int*)SM;                 // NKEY words
        float (*smw)[9] = (float(*)[9])(SM + 19664);
        int lane = tid & 31;
        for (int i = tid; i < NKEY; i += NTHR) h[i] = 0u;
        __syncthreads();
        for (int q = bid*NTHR + tid; q < NPIX/4; q += TOTTHR){
            int p = q*4;
            int b = p >> 18, rem = p & 262143;
            uchar4 q0 = *(const uchar4*)(g_qidx + ((size_t)(b*3+0)<<18) + rem);
            uchar4 q1 = *(const uchar4*)(g_qidx + ((size_t)(b*3+1)<<18) + rem);
            uchar4 q2 = *(const uchar4*)(g_qidx + ((size_t)(b*3+2)<<18) + rem);
            int k0 = q0.x + 17*q1.x + 289*q2.x;
            int k1 = q0.y + 17*q1.y + 289*q2.y;
            int k2 = q0.z + 17*q1.z + 289*q2.z;
            int k3 = q0.w + 17*q1.w + 289*q2.w;
            *(ushort4*)(g_key + p) = make_ushort4((unsigned short)k0, (unsigned short)k1,
                                                  (unsigned short)k2, (unsigned short)k3);
            #pragma unroll
            for (int s = 0; s < 4; s++){
                int kk = s==0?k0 : s==1?k1 : s==2?k2 : k3;
                unsigned int mm = __match_any_sync(0xffffffffu, kk);
                if ((mm & (mm-1u)) == 0u || lane == (__ffs(mm)-1))
                    atomicAdd(&h[kk], (unsigned int)__popc(mm));
            }
        }
        __syncthreads();
        float m[9];
        #pragma unroll
        for (int j = 0; j < 9; j++) m[j] = 0.f;
        for (int i = tid; i < NKEY; i += NTHR){
            unsigned int v = h[i];
            if (v){
                atomicAdd(&g_hist[i], v);
                float w = (float)v;
                float x0 = (float)(i % 17) * 0.0625f;
                float x1 = (float)((i/17) % 17) * 0.0625f;
                float x2 = (float)(i / 289) * 0.0625f;
                m[0]+=w*x0; m[1]+=w*x1; m[2]+=w*x2;
                m[3]+=w*x0*x0; m[4]+=w*x0*x1; m[5]+=w*x0*x2;
                m[6]+=w*x1*x1; m[7]+=w*x1*x2; m[8]+=w*x2*x2;
            }
        }
        #pragma unroll
        for (int j = 0; j < 9; j++){
            float v = m[j];
            #pragma unroll
            for (int off = 16; off; off >>= 1) v += __shfl_down_sync(0xffffffffu, v, off);
            if ((tid & 31) == 0) smw[tid>>5][j] = v;
        }
        __syncthreads();
        if (tid < 9){
            float a = 0.f;
            for (int w8 = 0; w8 < 8; w8++) a += smw[w8][tid];
            if (a != 0.f) atomicAdd(&g_acc[OF_XMOM + tid], (double)a);
        }
    }
    gridbar();

    // ---------- Phase C: h1 second moments ----------
    if (bid < 8){
        float* sA1 = (float*)SM;               // 48
        float* sB1 = (float*)(SM + 192);       // 16
        float* h1s = (float*)(SM + 256);       // 256*17
        float* ws  = (float*)(SM + 256 + 17408); // 256
        bn1_affine_block(pw1, pb1, g1, be1, sA1, sB1);
        __syncthreads();
        int pi = 0, pj = 0;
        if (tid >= 16 && tid < 152){
            int p = tid - 16, i = 0;
            while (p >= 16 - i){ p -= 16 - i; i++; }
            pi = i; pj = i + p;
        }
        int k0 = bid * 615;
        int k1 = k0 + 615; if (k1 > NKEY) k1 = NKEY;
        double acc = 0.0;
        for (int base = k0; base < k1; base += NTHR){
            int tt = base + tid;
            float w = 0.f;
            if (tt < k1){
                w = (float)g_hist[tt];
                float x0 = (float)(tt % 17) * 0.0625f;
                float x1 = (float)((tt/17) % 17) * 0.0625f;
                float x2 = (float)(tt / 289) * 0.0625f;
                #pragma unroll
                for (int o = 0; o < 16; o++){
                    float hh = sB1[o] + sA1[o*3]*x0 + sA1[o*3+1]*x1 + sA1[o*3+2]*x2;
                    h1s[tid*17+o] = hh >= 0.f ? hh : 0.01f*hh;
                }
            }
            ws[tid] = w;
            __syncthreads();
            int cnt = k1 - base; if (cnt > NTHR) cnt = NTHR;
            float f0 = 0.f, f1 = 0.f;
            if (tid < 16){
                int k = 0;
                for (; k + 1 < cnt; k += 2){
                    f0 += ws[k]   * h1s[k*17+tid];
                    f1 += ws[k+1] * h1s[(k+1)*17+tid];
                }
                if (k < cnt) f0 += ws[k]*h1s[k*17+tid];
            } else if (tid < 152){
                int k = 0;
                for (; k + 1 < cnt; k += 2){
                    f0 += ws[k]   * h1s[k*17+pi]     * h1s[k*17+pj];
                    f1 += ws[k+1] * h1s[(k+1)*17+pi] * h1s[(k+1)*17+pj];
                }
                if (k < cnt) f0 += ws[k]*h1s[k*17+pi]*h1s[k*17+pj];
            }
            acc += (double)(f0 + f1);
            __syncthreads();
        }
        if (tid < 152 && acc != 0.0) atomicAdd(&g_acc[OF_MOM2 + tid], acc);
    }
    gridbar();

    // ---------- Phase D: prep LUT + iter0 p-moments ----------
    if (bid < 20){
        float* sA1 = (float*)SM;                 // 48
        float* sB1 = (float*)(SM + 192);         // 16
        float* sA2 = (float*)(SM + 256);         // 256
        float* sB2 = (float*)(SM + 1280);        // 16
        double* mu = (double*)(SM + 1344);       // 16
        double (*cov)[16] = (double(*)[16])(SM + 1472);  // 16x16
        double* sm = (double*)(SM + 3520);       // 32
        bn1_affine_block(pw1, pb1, g1, be1, sA1, sB1);
        if (tid < 32) sm[tid] = 0.0;
        const double N = (double)NPIX;
        if (tid < 16) mu[tid] = g_acc[OF_MOM2 + tid] / N;
        __syncthreads();
        if (tid >= 16 && tid < 152){
            int p = tid - 16, i = 0;
            while (p >= 16 - i){ p -= 16 - i; i++; }
            int pi = i, pj = i + p;
            double c = g_acc[OF_MOM2 + tid]/N - mu[pi]*mu[pj];
            cov[pi][pj] = c; cov[pj][pi] = c;
        }
        __syncthreads();
        if (tid < 16){
            int o = tid;
            double wv[16];
            double m = (double)pb2[o], v = 0.0;
            for (int i = 0; i < 16; i++){ wv[i] = pw2[o*16+i]; m += wv[i]*mu[i]; }
            for (int i = 0; i < 16; i++) for (int j = 0; j < 16; j++) v += wv[i]*wv[j]*cov[i][j];
            double s = (1.0 / sqrt(v + 1e-5)) * (double)g2[o];
            for (int i = 0; i < 16; i++) sA2[o*16+i] = (float)(wv[i]*s);
            sB2[o] = (float)(((double)pb2[o]-m)*s + (double)be2[o]);
        }
        __syncthreads();
        int t = bid*NTHR + tid;
        float s1[16], s2[16];
        if (t < NKEY){
            float w = (float)g_hist[t];
            float x0 = (float)(t % 17) * 0.0625f;
            float x1 = (float)((t/17) % 17) * 0.0625f;
            float x2 = (float)(t / 289) * 0.0625f;
            float h1[16];
            #pragma unroll
            for (int o = 0; o < 16; o++){
                float hh = sB1[o] + sA1[o*3]*x0 + sA1[o*3+1]*x1 + sA1[o*3+2]*x2;
                h1[o] = hh >= 0.f ? hh : 0.01f*hh;
            }
            float pv[16];
            #pragma unroll
            for (int o = 0; o < 16; o++){
                float p = sB2[o];
                #pragma unroll
                for (int i = 0; i < 16; i++) p += sA2[o*16+i]*h1[i];
                p = p >= 0.f ? p : 0.01f*p;
                pv[o] = p;
                s1[o] = w*p; s2[o] = w*p*p;
            }
            st16(g_prepLUT + t*16, pv);
        } else {
            #pragma unroll
            for (int o = 0; o < 16; o++){ s1[o] = 0.f; s2[o] = 0.f; }
        }
        red16(s1, sm);
        red16(s2, sm + 16);
        __syncthreads();
        if (tid < 16)       atomicAdd(&g_acc[OF_M0P  + tid],      sm[tid]);
        else if (tid < 32)  atomicAdd(&g_acc[OF_M0PP + tid - 16], sm[tid]);
    }
    gridbar();

    // ---------- Phase E: conv pyramid (sdw persists in SM through all levels) ----------
    float* sdw = (float*)SM;
    for (int i = tid; i < 2304; i += NTHR) sdw[i] = dw[i];
    __syncthreads();
    // level 0 -> 1 (via key + LUT)
    for (int cell = bid*NTHR + tid; cell < 171*171*8; cell += TOTTHR){
        int b = cell / (171*171);
        int pos = cell % (171*171);
        int u = pos / 171, v = pos % 171;
        float acc[16];
        #pragma unroll
        for (int o = 0; o < 16; o++) acc[o] = 0.f;
        for (int ky = 0; ky < 3; ky++){
            int iy = 3*u - 1 + ky; if (iy < 0 || iy >= 512) continue;
            for (int kx = 0; kx < 3; kx++){
                int ix = 3*v - 1 + kx; if (ix < 0 || ix >= 512) continue;
                int key = g_key[(b<<18) + iy*512 + ix];
                float pv[16];
                ld16(g_prepLUT + key*16, pv);
                #pragma unroll
                for (int c = 0; c < 16; c++){
                    #pragma unroll
                    for (int o = 0; o < 16; o++)
                        acc[o] += sdw[(o*16+c)*9 + ky*3 + kx] * pv[c];
                }
            }
        }
        st16(g_d1 + ((size_t)(b*171+u)*171 + v)*16, acc);
    }
    gridbar();
    {   // 1 -> 2
        int cell = bid*NTHR + tid;
        if (cell < 57*57*8){
            int b = cell / (57*57), pos = cell % (57*57);
            conv_cell(g_d1, g_d2, sdw, b, 171, 57, pos/57, pos%57);
        }
    }
    gridbar();
    {   // 2 -> 3
        int cell = bid*NTHR + tid;
        if (cell < 19*19*8){
            int b = cell / (19*19), pos = cell % (19*19);
            conv_cell(g_d2, g_d3, sdw, b, 57, 19, pos/19, pos%19);
        }
    }
    gridbar();
    {   // 3 -> 4
        int cell = bid*NTHR + tid;
        if (cell < 7*7*8){
            int b = cell / 49, pos = cell % 49;
            conv_cell(g_d3, g_d4, sdw, b, 19, 7, pos/7, pos%7);
        }
    }
    gridbar();
    {   // 4 -> 5
        int cell = bid*NTHR + tid;
        if (cell < 3*3*8){
            int b = cell / 9, pos = cell % 9;
            conv_cell(g_d4, g_d5, sdw, b, 7, 3, pos/3, pos%3);
        }
    }
    gridbar();
    {   // 5 -> 6
        int cell = bid*NTHR + tid;
        if (cell < 8)
            conv_cell(g_d5, g_d6, sdw, cell, 3, 1, 0, 0);
    }
    gridbar();

    // ---------- Phase F: fused stats ----------
    {
        double* sm = (double*)SM;   // 32 doubles (convs done; safe to reuse)
        for (int vb = bid; vb < 521*8; vb += NBLK){
            int bx = vb % 521;
            int b  = vb / 521;
            __syncthreads();
            if (tid < 32) sm[tid] = 0.0;
            __syncthreads();
            if (bx < 256){
                float acc[16];
                #pragma unroll
                for (int j = 0; j < 16; j++) acc[j] = 0.f;
                int base = (b<<18) + bx*1024;
                for (int k = 0; k < 4; k++){
                    int p = base + k*256 + tid;
                    int rem = p & 262143, y = rem >> 9, xx = rem & 511;
                    int key = g_key[p];
                    float pv[16], z[16];
                    ld16(g_prepLUT + key*16, pv);
                    int rz = (y*171) >> 9, cz = (xx*171) >> 9;
                    ld16(g_d1 + ((size_t)(b*171+rz)*171 + cz)*16, z);
                    #pragma unroll
                    for (int j = 0; j < 16; j++) acc[j] += pv[j]*z[j];
                }
                red16(acc, sm);
                __syncthreads();
                if (tid < 16) atomicAdd(&g_acc[OF_PZ + tid], sm[tid]);
            } else {
                int task = 0;
                while (bx >= c_tstart[task+1]) task++;
                int sub = bx - c_tstart[task];
                int nblk = c_tstart[task+1] - c_tstart[task];
                if (task < 6){
                    int lvl = task + 1;
                    int n = c_n[lvl];
                    const float* dz = dlevel(lvl);
                    int cells = n*n;
                    float s1[16], s2[16];
                    #pragma unroll
                    for (int j = 0; j < 16; j++){ s1[j] = 0.f; s2[j] = 0.f; }
                    for (int cell = sub*NTHR + tid; cell < cells; cell += nblk*NTHR){
                        int r = cell / n, c = cell % n;
                        float w = (float)((wlo(n,r+1)-wlo(n,r)) * (wlo(n,c+1)-wlo(n,c)));
                        float z[16];
                        ld16(dz + ((size_t)(b*n+r)*n + c)*16, z);
                        #pragma unroll
                        for (int j = 0; j < 16; j++){ s1[j] += w*z[j]; s2[j] += w*z[j]*z[j]; }
                    }
                    red16(s1, sm); red16(s2, sm + 16);
                    __syncthreads();
                    if (tid < 16)       atomicAdd(&g_acc[OF_ZM  + (lvl-1)*16 + tid],      sm[tid]);
                    else if (tid < 32)  atomicAdd(&g_acc[OF_ZM2 + (lvl-1)*16 + tid - 16], sm[tid]);
                } else {
                    int it = task - 5;
                    int np = c_n[it], nz = c_n[it+1];
                    const float* dp = dlevel(it);
                    const float* dz = dlevel(it+1);
                    int cells = np*np;
                    float acc[16];
                    #pragma unroll
                    for (int j = 0; j < 16; j++) acc[j] = 0.f;
                    for (int cell = sub*NTHR + tid; cell < cells; cell += nblk*NTHR){
                        int r = cell / np, c = cell % np;
                        float p[16];
                        ld16(dp + ((size_t)(b*np+r)*np + c)*16, p);
                        int y0 = wlo(np,r), y1 = wlo(np,r+1);
                        int x0 = wlo(np,c), x1 = wlo(np,c+1);
                        float zs[16];
                        #pragma unroll
                        for (int j = 0; j < 16; j++) zs[j] = 0.f;
                        for (int y = y0; y < y1; y++){
                            int s = (y*nz) >> 9;
                            for (int xx = x0; xx < x1; xx++){
                                int t2 = (xx*nz) >> 9;
                                float z[16];
                                ld16(dz + ((size_t)(b*nz+s)*nz + t2)*16, z);
                                #pragma unroll
                                for (int j = 0; j < 16; j++) zs[j] += z[j];
                            }
                        }
                        #pragma unroll
                        for (int j = 0; j < 16; j++) acc[j] += p[j]*zs[j];
                    }
                    red16(acc, sm);
                    __syncthreads();
                    if (tid < 16) atomicAdd(&g_acc[OF_PZ + it*16 + tid], sm[tid]);
                }
            }
        }
    }
    gridbar();

    // ---------- Phase G: BN fold ----------
    if (bid == 0 && tid < 192){
        int t = tid;
        int iter = t / 32, ch = t % 32, g = ch >> 1, o = ch & 1;
        const double N = (double)NPIX;
        double mp, mpp;
        if (iter == 0){ mp = g_acc[OF_M0P + g]; mpp = g_acc[OF_M0PP + g]; }
        else { mp = g_acc[OF_ZM + (iter-1)*16 + g]; mpp = g_acc[OF_ZM2 + (iter-1)*16 + g]; }
        double mz  = g_acc[OF_ZM  + iter*16 + g];
        double mzz = g_acc[OF_ZM2 + iter*16 + g];
        double mpz = g_acc[OF_PZ  + iter*16 + g];
        mp/=N; mpp/=N; mz/=N; mzz/=N; mpz/=N;
        double a = (double)sw[g*4 + o*2 + 0], bb = (double)sw[g*4 + o*2 + 1];
        double mean = a*mp + bb*mz;
        double m2 = a*a*mpp + 2.0*a*bb*mpz + bb*bb*mzz;
        double var = m2 - mean*mean;
        double s = (double)gs[ch] * (1.0 / sqrt(var + 1e-5));
        g_S[t] = (float)s;
        g_T[t] = (float)((double)bs[ch] - mean*s);
    }
    gridbar();

    // ---------- Phase H: final accumulate + write ----------
    {
        float* ssw = (float*)SM;            // 64
        float* sS  = (float*)(SM + 256);    // 192
        float* sT  = (float*)(SM + 1024);   // 192
        if (tid < 64) ssw[tid] = sw[tid];
        if (tid < 192){ sS[tid] = g_S[tid]; sT[tid] = g_T[tid]; }
        __syncthreads();
        for (int p = bid*NTHR + tid; p < NPIX; p += TOTTHR){
            int b = p >> 18, rem = p & 262143, y = rem >> 9, xx = rem & 511;
            float prev[16];
            int key = g_key[p];
            ld16(g_prepLUT + key*16, prev);
            float sc[32];
            #pragma unroll
            for (int c = 0; c < 32; c++) sc[c] = 0.f;
            #pragma unroll
            for (int iter = 0; iter < 6; iter++){
                int nz = c_n[iter+1];
                int rz = (y*nz) >> 9, cz = (xx*nz) >> 9;
                float z[16];
                ld16(dlevel(iter+1) + ((size_t)(b*nz+rz)*nz + cz)*16, z);
                #pragma unroll
                for (int g = 0; g < 16; g++){
                    float zv = z[g];
                    float pv = prev[g];
                    int c0 = iter*32 + 2*g;
                    float v0 = (ssw[g*4+0]*pv + ssw[g*4+1]*zv)*sS[c0]   + sT[c0];
                    float v1 = (ssw[g*4+2]*pv + ssw[g*4+3]*zv)*sS[c0+1] + sT[c0+1];
                    sc[2*g]   += v0 >= 0.f ? v0 : 0.01f*v0;
                    sc[2*g+1] += v1 >= 0.f ? v1 : 0.01f*v1;
                    prev[g] = zv;
                }
            }
            size_t ob = ((size_t)b*32) << 18;
            #pragma unroll
            for (int c = 0; c < 32; c++)
                __stcs(out + ob + ((size_t)c << 18) + rem, sc[c]);
        }
    }
}

// ---------------- launcher: ONE kernel ----------------
extern "C" void kernel_launch(void* const* d_in, const int* in_sizes, int n_in,
                              void* d_out, int out_size){
    const float* x   = (const float*)d_in[0];
    const float* pw1 = (const float*)d_in[1];
    const float* pb1 = (const float*)d_in[2];
    const float* g1  = (const float*)d_in[3];
    const float* be1 = (const float*)d_in[4];
    const float* pw2 = (const float*)d_in[5];
    const float* pb2 = (const float*)d_in[6];
    const float* g2  = (const float*)d_in[7];
    const float* be2 = (const float*)d_in[8];
    const float* dw  = (const float*)d_in[9];
    const float* sw  = (const float*)d_in[10];
    const float* gs  = (const float*)d_in[11];
    const float* bs  = (const float*)d_in[12];
    float* out = (float*)d_out;
    (void)in_sizes; (void)n_in; (void)out_size;

    k_all<<<NBLK, NTHR>>>(x, pw1, pb1, g1, be1, pw2, pb2, g2, be2,
                          dw, sw, gs, bs, out);
}

// round 17
// speedup vs baseline: 1.0020x; 1.0020x over previous
#include <cuda_runtime.h>
#include <math.h>

#define NPIX 2097152
#define NKEY 4913
#define NBLK 296
#define NTHR 256
#define TOTTHR (NBLK*NTHR)

// double accumulator offsets
#define OF_XMOM 0
#define OF_M0P  16
#define OF_M0PP 32
#define OF_MOM2 48
#define OF_ZM   200
#define OF_ZM2  296
#define OF_PZ   392
#define ACCN    512

__device__ unsigned char  g_qidx[8*3*512*512];
__device__ unsigned short g_key [NPIX];
__device__ unsigned int   g_hist[NKEY];
__device__ double g_acc[ACCN];
__device__ float  g_prepLUT[NKEY*16];
__device__ float  g_S[192], g_T[192];
// pyramid levels, CHANNEL-LAST: d[((b*n+y)*n+x)*16 + g]
__device__ float  g_d1[8*171*171*16];
__device__ float  g_d2[8*57*57*16];
__device__ float  g_d3[8*19*19*16];
__device__ float  g_d4[8*7*7*16];
__device__ float  g_d5[8*3*3*16];
__device__ float  g_d6[8*16];

// software grid barrier state (monotonic generation -> replay-safe)
__device__ unsigned int g_barcnt = 0;
__device__ unsigned int g_bargen = 0;

__constant__ int c_n[7] = {512,171,57,19,7,3,1};
// stats task layout: bx<256 -> cross0; then zstats lvl1..6, crossN it1..5
__constant__ int c_tstart[12] = {256,371,384,386,387,388,389,504,517,519,520,521};

__device__ __forceinline__ const float* dlevel(int l){
    switch(l){ case 1: return g_d1; case 2: return g_d2; case 3: return g_d3;
               case 4: return g_d4; case 5: return g_d5; default: return g_d6; }
}
__device__ __forceinline__ int qbin(float v){
    return (int)rintf(__fmul_rn(__fmul_rn(v, 255.0f), 0.0625f));
}
__device__ __forceinline__ unsigned char amax17(const unsigned int s[5]){
    int best = 0; unsigned int bc = s[0] & 255u;
    #pragma unroll
    for (int b = 1; b < 17; b++){
        unsigned int c = (s[b>>2] >> ((b&3)*8)) & 255u;
        if (c > bc){ bc = c; best = b; }
    }
    return (unsigned char)best;
}
__device__ __forceinline__ void ld16(const float* p, float* v){
    const float4* q = (const float4*)p;
    float4 a=q[0], b=q[1], c=q[2], d=q[3];
    v[0]=a.x; v[1]=a.y; v[2]=a.z; v[3]=a.w; v[4]=b.x; v[5]=b.y; v[6]=b.z; v[7]=b.w;
    v[8]=c.x; v[9]=c.y; v[10]=c.z; v[11]=c.w; v[12]=d.x; v[13]=d.y; v[14]=d.z; v[15]=d.w;
}
__device__ __forceinline__ void st16(float* p, const float* v){
    float4* q = (float4*)p;
    q[0]=make_float4(v[0],v[1],v[2],v[3]);   q[1]=make_float4(v[4],v[5],v[6],v[7]);
    q[2]=make_float4(v[8],v[9],v[10],v[11]); q[3]=make_float4(v[12],v[13],v[14],v[15]);
}
__device__ __forceinline__ void red16(const float* a, double* sm){
    #pragma unroll
    for (int j = 0; j < 16; j++){
        float v = a[j];
        #pragma unroll
        for (int off = 16; off; off >>= 1) v += __shfl_down_sync(0xffffffffu, v, off);
        if ((threadIdx.x & 31) == 0 && v != 0.f) atomicAdd(&sm[j], (double)v);
    }
}
__device__ __forceinline__ int wlo(int n, int r){ return (r*512 + n - 1)/n; }

__device__ __forceinline__ void gridbar(){
    __syncthreads();
    if (threadIdx.x == 0){
        __threadfence();
        unsigned int gen = *(volatile unsigned int*)&g_bargen;
        if (atomicAdd(&g_barcnt, 1u) == NBLK - 1u){
            g_barcnt = 0u;
            __threadfence();
            *(volatile unsigned int*)&g_bargen = gen + 1u;
        } else {
            while (*(volatile unsigned int*)&g_bargen == gen) __nanosleep(32);
        }
    }
    __syncthreads();
}

// BN1 affine from accumulated x-moments; threads 0..15 fill sA1[48], sB1[16]
__device__ __forceinline__ void bn1_affine_block(
    const float* __restrict__ pw1, const float* __restrict__ pb1,
    const float* __restrict__ g1,  const float* __restrict__ be1,
    float* sA1, float* sB1){
    int o = threadIdx.x;
    if (o < 16){
        double mom[9];
        #pragma unroll
        for (int i = 0; i < 9; i++) mom[i] = g_acc[OF_XMOM + i];
        const double N = (double)NPIX;
        double mu[3] = {mom[0]/N, mom[1]/N, mom[2]/N};
        double cov[3][3];
        cov[0][0]=mom[3]/N-mu[0]*mu[0]; cov[0][1]=mom[4]/N-mu[0]*mu[1]; cov[0][2]=mom[5]/N-mu[0]*mu[2];
        cov[1][1]=mom[6]/N-mu[1]*mu[1]; cov[1][2]=mom[7]/N-mu[1]*mu[2]; cov[2][2]=mom[8]/N-mu[2]*mu[2];
        cov[1][0]=cov[0][1]; cov[2][0]=cov[0][2]; cov[2][1]=cov[1][2];
        double wv[3] = {pw1[o*3], pw1[o*3+1], pw1[o*3+2]};
        double m = (double)pb1[o] + wv[0]*mu[0] + wv[1]*mu[1] + wv[2]*mu[2];
        double v = 0.0;
        for (int i = 0; i < 3; i++) for (int j = 0; j < 3; j++) v += wv[i]*wv[j]*cov[i][j];
        double s = (1.0 / sqrt(v + 1e-5)) * (double)g1[o];
        sA1[o*3+0]=(float)(wv[0]*s); sA1[o*3+1]=(float)(wv[1]*s); sA1[o*3+2]=(float)(wv[2]*s);
        sB1[o]=(float)(((double)pb1[o]-m)*s + (double)be1[o]);
    }
}

#define SWZ(c) ((c) + ((c)>>5))
#define SROW 528

// conv cell helper (channel-last)
__device__ __forceinline__ void conv_cell(const float* __restrict__ in, float* __restrict__ out,
                                          const float* __restrict__ sdw, int b, int n, int m,
                                          int u, int v){
    float acc[16];
    #pragma unroll
    for (int o = 0; o < 16; o++) acc[o] = 0.f;
    for (int ky = 0; ky < 3; ky++){
        int iy = 3*u - 1 + ky; if (iy < 0 || iy >= n) continue;
        for (int kx = 0; kx < 3; kx++){
            int ix = 3*v - 1 + kx; if (ix < 0 || ix >= n) continue;
            float pv[16];
            ld16(in + ((size_t)(b*n+iy)*n + ix)*16, pv);
            #pragma unroll
            for (int c = 0; c < 16; c++){
                #pragma unroll
                for (int o = 0; o < 16; o++)
                    acc[o] += sdw[(o*16+c)*9 + ky*3 + kx] * pv[c];
            }
        }
    }
    st16(out + ((size_t)(b*m+u)*m + v)*16, acc);
}

// =================== THE single persistent kernel ===================
__global__ void __launch_bounds__(NTHR, 2) k_all(
    const float* __restrict__ x,
    const float* __restrict__ pw1, const float* __restrict__ pb1,
    const float* __restrict__ g1,  const float* __restrict__ be1,
    const float* __restrict__ pw2, const float* __restrict__ pb2,
    const float* __restrict__ g2,  const float* __restrict__ be2,
    const float* __restrict__ dw,  const float* __restrict__ sw,
    const float* __restrict__ gs,  const float* __restrict__ bs,
    float* __restrict__ out)
{
    __shared__ __align__(16) unsigned char SM[21248];
    const int tid = threadIdx.x;
    const int bid = blockIdx.x;

    // ---------- Phase A: zero accumulators + 11x11 mode pool ----------
    if (bid == 0){
        for (int i = tid; i < NKEY; i += NTHR) g_hist[i] = 0u;
        for (int i = tid; i < ACCN; i += NTHR) g_acc[i] = 0.0;
    }
    {
        unsigned int* sh = (unsigned int*)SM;
        for (int tile = bid; tile < 384; tile += NBLK){
            int plane = tile / 16;
            int y0    = (tile % 16) * 32;
            const float* xp = x + (size_t)plane * 262144;
            unsigned char* qp = g_qidx + (size_t)plane * 262144;
            __syncthreads();
            for (int i = tid; i < 5*SROW; i += NTHR) sh[i] = 0u;
            __syncthreads();
            const int c0 = tid * 2;
            const int sc0 = SWZ(c0);           // c0 even -> SWZ(c0+1)=sc0+1
            for (int dy = -5; dy <= 5; dy++){
                int ry = y0 + dy; ry = ry < 0 ? -ry : (ry > 511 ? 1022 - ry : ry);
                float2 f = *(const float2*)(xp + ry*512 + c0);
                int b0 = qbin(f.x), b1 = qbin(f.y);
                sh[(b0>>2)*SROW + sc0]     += 1u << ((b0&3)*8);
                sh[(b1>>2)*SROW + sc0 + 1] += 1u << ((b1&3)*8);
            }
            __syncthreads();
            for (int r = 0; r < 32; r++){
                int y = y0 + r;
                if (r > 0){
                    int yr = y - 6; yr = yr < 0 ? -yr : yr;
                    int ya = y + 5; ya = ya > 511 ? 1022 - ya : ya;
                    float2 fr = *(const float2*)(xp + yr*512 + c0);
                    float2 fa = *(const float2*)(xp + ya*512 + c0);
                    int b0 = qbin(fr.x), b1 = qbin(fr.y);
                    sh[(b0>>2)*SROW + sc0]     -= 1u << ((b0&3)*8);
                    sh[(b1>>2)*SROW + sc0 + 1] -= 1u << ((b1&3)*8);
                    b0 = qbin(fa.x); b1 = qbin(fa.y);
                    sh[(b0>>2)*SROW + sc0]     += 1u << ((b0&3)*8);
                    sh[(b1>>2)*SROW + sc0 + 1] += 1u << ((b1&3)*8);
                    __syncthreads();
                }
                unsigned int s[5];
                #pragma unroll
                for (int w = 0; w < 5; w++){
                    unsigned int a = 0;
                    #pragma unroll
                    for (int j = -5; j <= 5; j++){
                        int cj = c0 + j; cj = cj < 0 ? -cj : (cj > 511 ? 1022 - cj : cj);
                        a += sh[w*SROW + SWZ(cj)];
                    }
                    s[w] = a;
                }
                unsigned char m0 = amax17(s);
                {
                    int c = c0 + 1;
                    int cr = c - 6; cr = cr < 0 ? -cr : cr;
                    int ca = c + 5; ca = ca > 511 ? 1022 - ca : ca;
                    #pragma unroll
                    for (int w = 0; w < 5; w++)
                        s[w] += sh[w*SROW + SWZ(ca)] - sh[w*SROW + SWZ(cr)];
                }
                unsigned char m1 = amax17(s);
                *(uchar2*)(qp + y*512 + c0) = make_uchar2(m0, m1);
                __syncthreads();
            }
        }
    }
    gridbar();

    // ---------- Phase B: keys + histogram + x-moments ----------
    {
        unsigned int* h = (unsigned int*)SM;                 // NKEY words
        float (*smw)[9] = (float(*)[9])(SM + 19664);
        int lane = tid & 31;
        for (int i = tid; i < NKEY; i += NTHR) h[i] = 0u;
        __syncthreads();
        for (int q = bid*NTHR + tid; q < NPIX/4; q += TOTTHR){
            int p = q*4;
            int b = p >> 18, rem = p & 262143;
            uchar4 q0 = *(const uchar4*)(g_qidx + ((size_t)(b*3+0)<<18) + rem);
            uchar4 q1 = *(const uchar4*)(g_qidx + ((size_t)(b*3+1)<<18) + rem);
            uchar4 q2 = *(const uchar4*)(g_qidx + ((size_t)(b*3+2)<<18) + rem);
            int k0 = q0.x + 17*q1.x + 289*q2.x;
            int k1 = q0.y + 17*q1.y + 289*q2.y;
            int k2 = q0.z + 17*q1.z + 289*q2.z;
            int k3 = q0.w + 17*q1.w + 289*q2.w;
            *(ushort4*)(g_key + p) = make_ushort4((unsigned short)k0, (unsigned short)k1,
                                                  (unsigned short)k2, (unsigned short)k3);
            #pragma unroll
            for (int s = 0; s < 4; s++){
                int kk = s==0?k0 : s==1?k1 : s==2?k2 : k3;
                unsigned int mm = __match_any_sync(0xffffffffu, kk);
                if ((mm & (mm-1u)) == 0u || lane == (__ffs(mm)-1))
                    atomicAdd(&h[kk], (unsigned int)__popc(mm));
            }
        }
        __syncthreads();
        float m[9];
        #pragma unroll
        for (int j = 0; j < 9; j++) m[j] = 0.f;
        for (int i = tid; i < NKEY; i += NTHR){
            unsigned int v = h[i];
            if (v){
                atomicAdd(&g_hist[i], v);
                float w = (float)v;
                float x0 = (float)(i % 17) * 0.0625f;
                float x1 = (float)((i/17) % 17) * 0.0625f;
                float x2 = (float)(i / 289) * 0.0625f;
                m[0]+=w*x0; m[1]+=w*x1; m[2]+=w*x2;
                m[3]+=w*x0*x0; m[4]+=w*x0*x1; m[5]+=w*x0*x2;
                m[6]+=w*x1*x1; m[7]+=w*x1*x2; m[8]+=w*x2*x2;
            }
        }
        #pragma unroll
        for (int j = 0; j < 9; j++){
            float v = m[j];
            #pragma unroll
            for (int off = 16; off; off >>= 1) v += __shfl_down_sync(0xffffffffu, v, off);
            if ((tid & 31) == 0) smw[tid>>5][j] = v;
        }
        __syncthreads();
        if (tid < 9){
            float a = 0.f;
            for (int w8 = 0; w8 < 8; w8++) a += smw[w8][tid];
            if (a != 0.f) atomicAdd(&g_acc[OF_XMOM + tid], (double)a);
        }
    }
    gridbar();

    // ---------- Phase C: h1 second moments ----------
    if (bid < 8){
        float* sA1 = (float*)SM;               // 48
        float* sB1 = (float*)(SM + 192);       // 16
        float* h1s = (float*)(SM + 256);       // 256*17
        float* ws  = (float*)(SM + 256 + 17408); // 256
        bn1_affine_block(pw1, pb1, g1, be1, sA1, sB1);
        __syncthreads();
        int pi = 0, pj = 0;
        if (tid >= 16 && tid < 152){
            int p = tid - 16, i = 0;
            while (p >= 16 - i){ p -= 16 - i; i++; }
            pi = i; pj = i + p;
        }
        int k0 = bid * 615;
        int k1 = k0 + 615; if (k1 > NKEY) k1 = NKEY;
        double acc = 0.0;
        for (int base = k0; base < k1; base += NTHR){
            int tt = base + tid;
            float w = 0.f;
            if (tt < k1){
                w = (float)g_hist[tt];
                float x0 = (float)(tt % 17) * 0.0625f;
                float x1 = (float)((tt/17) % 17) * 0.0625f;
                float x2 = (float)(tt / 289) * 0.0625f;
                #pragma unroll
                for (int o = 0; o < 16; o++){
                    float hh = sB1[o] + sA1[o*3]*x0 + sA1[o*3+1]*x1 + sA1[o*3+2]*x2;
                    h1s[tid*17+o] = hh >= 0.f ? hh : 0.01f*hh;
                }
            }
            ws[tid] = w;
            __syncthreads();
            int cnt = k1 - base; if (cnt > NTHR) cnt = NTHR;
            float f0 = 0.f, f1 = 0.f;
            if (tid < 16){
                int k = 0;
                for (; k + 1 < cnt; k += 2){
                    f0 += ws[k]   * h1s[k*17+tid];
                    f1 += ws[k+1] * h1s[(k+1)*17+tid];
                }
                if (k < cnt) f0 += ws[k]*h1s[k*17+tid];
            } else if (tid < 152){
                int k = 0;
                for (; k + 1 < cnt; k += 2){
                    f0 += ws[k]   * h1s[k*17+pi]     * h1s[k*17+pj];
                    f1 += ws[k+1] * h1s[(k+1)*17+pi] * h1s[(k+1)*17+pj];
                }
                if (k < cnt) f0 += ws[k]*h1s[k*17+pi]*h1s[k*17+pj];
            }
            acc += (double)(f0 + f1);
            __syncthreads();
        }
        if (tid < 152 && acc != 0.0) atomicAdd(&g_acc[OF_MOM2 + tid], acc);
    }
    gridbar();

    // ---------- Phase D: prep LUT + iter0 p-moments ----------
    if (bid < 20){
        float* sA1 = (float*)SM;                 // 48
        float* sB1 = (float*)(SM + 192);         // 16
        float* sA2 = (float*)(SM + 256);         // 256
        float* sB2 = (float*)(SM + 1280);        // 16
        double* mu = (double*)(SM + 1344);       // 16
        double (*cov)[16] = (double(*)[16])(SM + 1472);  // 16x16
        double* sm = (double*)(SM + 3520);       // 32
        bn1_affine_block(pw1, pb1, g1, be1, sA1, sB1);
        if (tid < 32) sm[tid] = 0.0;
        const double N = (double)NPIX;
        if (tid < 16) mu[tid] = g_acc[OF_MOM2 + tid] / N;
        __syncthreads();
        if (tid >= 16 && tid < 152){
            int p = tid - 16, i = 0;
            while (p >= 16 - i){ p -= 16 - i; i++; }
            int pi = i, pj = i + p;
            double c = g_acc[OF_MOM2 + tid]/N - mu[pi]*mu[pj];
            cov[pi][pj] = c; cov[pj][pi] = c;
        }
        __syncthreads();
        if (tid < 16){
            int o = tid;
            double wv[16];
            double m = (double)pb2[o], v = 0.0;
            for (int i = 0; i < 16; i++){ wv[i] = pw2[o*16+i]; m += wv[i]*mu[i]; }
            for (int i = 0; i < 16; i++) for (int j = 0; j < 16; j++) v += wv[i]*wv[j]*cov[i][j];
            double s = (1.0 / sqrt(v + 1e-5)) * (double)g2[o];
            for (int i = 0; i < 16; i++) sA2[o*16+i] = (float)(wv[i]*s);
            sB2[o] = (float)(((double)pb2[o]-m)*s + (double)be2[o]);
        }
        __syncthreads();
        int t = bid*NTHR + tid;
        float s1[16], s2[16];
        if (t < NKEY){
            float w = (float)g_hist[t];
            float x0 = (float)(t % 17) * 0.0625f;
            float x1 = (float)((t/17) % 17) * 0.0625f;
            float x2 = (float)(t / 289) * 0.0625f;
            float h1[16];
            #pragma unroll
            for (int o = 0; o < 16; o++){
                float hh = sB1[o] + sA1[o*3]*x0 + sA1[o*3+1]*x1 + sA1[o*3+2]*x2;
                h1[o] = hh >= 0.f ? hh : 0.01f*hh;
            }
            float pv[16];
            #pragma unroll
            for (int o = 0; o < 16; o++){
                float p = sB2[o];
                #pragma unroll
                for (int i = 0; i < 16; i++) p += sA2[o*16+i]*h1[i];
                p = p >= 0.f ? p : 0.01f*p;
                pv[o] = p;
                s1[o] = w*p; s2[o] = w*p*p;
            }
            st16(g_prepLUT + t*16, pv);
        } else {
            #pragma unroll
            for (int o = 0; o < 16; o++){ s1[o] = 0.f; s2[o] = 0.f; }
        }
        red16(s1, sm);
        red16(s2, sm + 16);
        __syncthreads();
        if (tid < 16)       atomicAdd(&g_acc[OF_M0P  + tid],      sm[tid]);
        else if (tid < 32)  atomicAdd(&g_acc[OF_M0PP + tid - 16], sm[tid]);
    }
    gridbar();

    // ---------- Phase E: conv pyramid (sdw persists in SM through all levels) ----------
    float* sdw = (float*)SM;
    for (int i = tid; i < 2304; i += NTHR) sdw[i] = dw[i];
    __syncthreads();
    // level 0 -> 1 (via key + LUT)
    for (int cell = bid*NTHR + tid; cell < 171*171*8; cell += TOTTHR){
        int b = cell / (171*171);
        int pos = cell % (171*171);
        int u = pos / 171, v = pos % 171;
        float acc[16];
        #pragma unroll
        for (int o = 0; o < 16; o++) acc[o] = 0.f;
        for (int ky = 0; ky < 3; ky++){
            int iy = 3*u - 1 + ky; if (iy < 0 || iy >= 512) continue;
            for (int kx = 0; kx < 3; kx++){
                int ix = 3*v - 1 + kx; if (ix < 0 || ix >= 512) continue;
                int key = g_key[(b<<18) + iy*512 + ix];
                float pv[16];
                ld16(g_prepLUT + key*16, pv);
                #pragma unroll
                for (int c = 0; c < 16; c++){
                    #pragma unroll
                    for (int o = 0; o < 16; o++)
                        acc[o] += sdw[(o*16+c)*9 + ky*3 + kx] * pv[c];
                }
            }
        }
        st16(g_d1 + ((size_t)(b*171+u)*171 + v)*16, acc);
    }
    gridbar();
    {   // 1 -> 2
        int cell = bid*NTHR + tid;
        if (cell < 57*57*8){
            int b = cell / (57*57), pos = cell % (57*57);
            conv_cell(g_d1, g_d2, sdw, b, 171, 57, pos/57, pos%57);
        }
    }
    gridbar();
    {   // 2 -> 3
        int cell = bid*NTHR + tid;
        if (cell < 19*19*8){
            int b = cell / (19*19), pos = cell % (19*19);
            conv_cell(g_d2, g_d3, sdw, b, 57, 19, pos/19, pos%19);
        }
    }
    gridbar();
    {   // 3 -> 4
        int cell = bid*NTHR + tid;
        if (cell < 7*7*8){
            int b = cell / 49, pos = cell % 49;
            conv_cell(g_d3, g_d4, sdw, b, 19, 7, pos/7, pos%7);
        }
    }
    gridbar();
    {   // 4 -> 5
        int cell = bid*NTHR + tid;
        if (cell < 3*3*8){
            int b = cell / 9, pos = cell % 9;
            conv_cell(g_d4, g_d5, sdw, b, 7, 3, pos/3, pos%3);
        }
    }
    gridbar();
    {   // 5 -> 6
        int cell = bid*NTHR + tid;
        if (cell < 8)
            conv_cell(g_d5, g_d6, sdw, cell, 3, 1, 0, 0);
    }
    gridbar();

    // ---------- Phase F: fused stats ----------
    {
        double* sm = (double*)SM;   // 32 doubles (convs done; safe to reuse)
        for (int vb = bid; vb < 521*8; vb += NBLK){
            int bx = vb % 521;
            int b  = vb / 521;
            __syncthreads();
            if (tid < 32) sm[tid] = 0.0;
            __syncthreads();
            if (bx < 256){
                float acc[16];
                #pragma unroll
                for (int j = 0; j < 16; j++) acc[j] = 0.f;
                int base = (b<<18) + bx*1024;
                for (int k = 0; k < 4; k++){
                    int p = base + k*256 + tid;
                    int rem = p & 262143, y = rem >> 9, xx = rem & 511;
                    int key = g_key[p];
                    float pv[16], z[16];
                    ld16(g_prepLUT + key*16, pv);
                    int rz = (y*171) >> 9, cz = (xx*171) >> 9;
                    ld16(g_d1 + ((size_t)(b*171+rz)*171 + cz)*16, z);
                    #pragma unroll
                    for (int j = 0; j < 16; j++) acc[j] += pv[j]*z[j];
                }
                red16(acc, sm);
                __syncthreads();
                if (tid < 16) atomicAdd(&g_acc[OF_PZ + tid], sm[tid]);
            } else {
                int task = 0;
                while (bx >= c_tstart[task+1]) task++;
                int sub = bx - c_tstart[task];
                int nblk = c_tstart[task+1] - c_tstart[task];
                if (task < 6){
                    int lvl = task + 1;
                    int n = c_n[lvl];
                    const float* dz = dlevel(lvl);
                    int cells = n*n;
                    float s1[16], s2[16];
                    #pragma unroll
                    for (int j = 0; j < 16; j++){ s1[j] = 0.f; s2[j] = 0.f; }
                    for (int cell = sub*NTHR + tid; cell < cells; cell += nblk*NTHR){
                        int r = cell / n, c = cell % n;
                        float w = (float)((wlo(n,r+1)-wlo(n,r)) * (wlo(n,c+1)-wlo(n,c)));
                        float z[16];
                        ld16(dz + ((size_t)(b*n+r)*n + c)*16, z);
                        #pragma unroll
                        for (int j = 0; j < 16; j++){ s1[j] += w*z[j]; s2[j] += w*z[j]*z[j]; }
                    }
                    red16(s1, sm); red16(s2, sm + 16);
                    __syncthreads();
                    if (tid < 16)       atomicAdd(&g_acc[OF_ZM  + (lvl-1)*16 + tid],      sm[tid]);
                    else if (tid < 32)  atomicAdd(&g_acc[OF_ZM2 + (lvl-1)*16 + tid - 16], sm[tid]);
                } else {
                    int it = task - 5;
                    int np = c_n[it], nz = c_n[it+1];
                    const float* dp = dlevel(it);
                    const float* dz = dlevel(it+1);
                    int cells = np*np;
                    float acc[16];
                    #pragma unroll
                    for (int j = 0; j < 16; j++) acc[j] = 0.f;
                    for (int cell = sub*NTHR + tid; cell < cells; cell += nblk*NTHR){
                        int r = cell / np, c = cell % np;
                        float p[16];
                        ld16(dp + ((size_t)(b*np+r)*np + c)*16, p);
                        int y0 = wlo(np,r), y1 = wlo(np,r+1);
                        int x0 = wlo(np,c), x1 = wlo(np,c+1);
                        float zs[16];
                        #pragma unroll
                        for (int j = 0; j < 16; j++) zs[j] = 0.f;
                        for (int y = y0; y < y1; y++){
                            int s = (y*nz) >> 9;
                            for (int xx = x0; xx < x1; xx++){
                                int t2 = (xx*nz) >> 9;
                                float z[16];
                                ld16(dz + ((size_t)(b*nz+s)*nz + t2)*16, z);
                                #pragma unroll
                                for (int j = 0; j < 16; j++) zs[j] += z[j];
                            }
                        }
                        #pragma unroll
                        for (int j = 0; j < 16; j++) acc[j] += p[j]*zs[j];
                    }
                    red16(acc, sm);
                    __syncthreads();
                    if (tid < 16) atomicAdd(&g_acc[OF_PZ + it*16 + tid], sm[tid]);
                }
            }
        }
    }
    gridbar();

    // ---------- Phase G: BN fold ----------
    if (bid == 0 && tid < 192){
        int t = tid;
        int iter = t / 32, ch = t % 32, g = ch >> 1, o = ch & 1;
        const double N = (double)NPIX;
        double mp, mpp;
        if (iter == 0){ mp = g_acc[OF_M0P + g]; mpp = g_acc[OF_M0PP + g]; }
        else { mp = g_acc[OF_ZM + (iter-1)*16 + g]; mpp = g_acc[OF_ZM2 + (iter-1)*16 + g]; }
        double mz  = g_acc[OF_ZM  + iter*16 + g];
        double mzz = g_acc[OF_ZM2 + iter*16 + g];
        double mpz = g_acc[OF_PZ  + iter*16 + g];
        mp/=N; mpp/=N; mz/=N; mzz/=N; mpz/=N;
        double a = (double)sw[g*4 + o*2 + 0], bb = (double)sw[g*4 + o*2 + 1];
        double mean = a*mp + bb*mz;
        double m2 = a*a*mpp + 2.0*a*bb*mpz + bb*bb*mzz;
        double var = m2 - mean*mean;
        double s = (double)gs[ch] * (1.0 / sqrt(var + 1e-5));
        g_S[t] = (float)s;
        g_T[t] = (float)((double)bs[ch] - mean*s);
    }
    gridbar();

    // ---------- Phase H: final accumulate + write ----------
    {
        float* ssw = (float*)SM;            // 64
        float* sS  = (float*)(SM + 256);    // 192
        float* sT  = (float*)(SM + 1024);   // 192
        if (tid < 64) ssw[tid] = sw[tid];
        if (tid < 192){ sS[tid] = g_S[tid]; sT[tid] = g_T[tid]; }
        __syncthreads();
        for (int p = bid*NTHR + tid; p < NPIX; p += TOTTHR){
            int b = p >> 18, rem = p & 262143, y = rem >> 9, xx = rem & 511;
            float prev[16];
            int key = g_key[p];
            ld16(g_prepLUT + key*16, prev);
            float sc[32];
            #pragma unroll
            for (int c = 0; c < 32; c++) sc[c] = 0.f;
            #pragma unroll
            for (int iter = 0; iter < 6; iter++){
                int nz = c_n[iter+1];
                int rz = (y*nz) >> 9, cz = (xx*nz) >> 9;
                float z[16];
                ld16(dlevel(iter+1) + ((size_t)(b*nz+rz)*nz + cz)*16, z);
                #pragma unroll
                for (int g = 0; g < 16; g++){
                    float zv = z[g];
                    float pv = prev[g];
                    int c0 = iter*32 + 2*g;
                    float v0 = (ssw[g*4+0]*pv + ssw[g*4+1]*zv)*sS[c0]   + sT[c0];
                    float v1 = (ssw[g*4+2]*pv + ssw[g*4+3]*zv)*sS[c0+1] + sT[c0+1];
                    sc[2*g]   += v0 >= 0.f ? v0 : 0.01f*v0;
                    sc[2*g+1] += v1 >= 0.f ? v1 : 0.01f*v1;
                    prev[g] = zv;
                }
            }
            size_t ob = ((size_t)b*32) << 18;
            #pragma unroll
            for (int c = 0; c < 32; c++)
                __stcs(out + ob + ((size_t)c << 18) + rem, sc[c]);
        }
    }
}

// ---------------- launcher: ONE kernel ----------------
extern "C" void kernel_launch(void* const* d_in, const int* in_sizes, int n_in,
                              void* d_out, int out_size){
    const float* x   = (const float*)d_in[0];
    const float* pw1 = (const float*)d_in[1];
    const float* pb1 = (const float*)d_in[2];
    const float* g1  = (const float*)d_in[3];
    const float* be1 = (const float*)d_in[4];
    const float* pw2 = (const float*)d_in[5];
    const float* pb2 = (const float*)d_in[6];
    const float* g2  = (const float*)d_in[7];
    const float* be2 = (const float*)d_in[8];
    const float* dw  = (const float*)d_in[9];
    const float* sw  = (const float*)d_in[10];
    const float* gs  = (const float*)d_in[11];
    const float* bs  = (const float*)d_in[12];
    float* out = (float*)d_out;
    (void)in_sizes; (void)n_in; (void)out_size;

    k_all<<<NBLK, NTHR>>>(x, pw1, pb1, g1, be1, pw2, pb2, g2, be2,
                          dw, sw, gs, bs, out);
}